// round 14
// baseline (speedup 1.0000x reference)
#include <cuda_runtime.h>
#include <cuda_fp16.h>
#include <math.h>
#include <stdint.h>

#define D_DIM 128
#define K_DIM 512
#define TM 64
#define NTHREADS 256
#define BETA_SM 10.0f

// smem byte offsets
#define USTRH 520                    // u row stride (halves) -> 1040 B
#define OFF_U 0                      // 64 x 1040 = 66560
#define OFF_LATH 66560               // 64 x 256 = 16384
#define ALSTR 256
#define OFF_EMB  82944               // 2 buffers x 128 x 264 = 67584
#define ESTR 264                     // k-row stride (bytes)
#define EBUF (128 * ESTR)            // 33792
#define OFF_ESQ  150528              // 512 x 4 = 2048
#define OFF_ROWSQ 152576             // 64 x 4 = 256
#define SMEM_BYTES 152832            // 1 CTA/SM

// ---------------- device globals (zero at load; self-reset each call) ----------------
__device__ double g_sq_sum;
__device__ double g_mind_sum;
__device__ unsigned int g_counts[K_DIM];
__device__ unsigned int g_done;

// ---------------- single fused kernel ----------------
__global__ void __launch_bounds__(NTHREADS, 1) vq_kernel(
    const float* __restrict__ latents,
    const float* __restrict__ emb,
    float* __restrict__ out_q,
    float* __restrict__ out_ind,
    float* __restrict__ out_soft,
    float* __restrict__ out_vq,
    float* __restrict__ out_ent,
    float* __restrict__ out_cm)
{
    extern __shared__ __align__(16) unsigned char smem[];
    __half*  s_uh    = (__half*)smem;                      // 64 x USTRH
    __half2* s_lath  = (__half2*)(smem + OFF_LATH);        // 64 x 64 (256 B rows)
    float*   s_esq   = (float*)(smem + OFF_ESQ);           // 512 (approx)
    float*   s_rowsq = (float*)(smem + OFF_ROWSQ);         // 64 (exact chains)

    const int tid = threadIdx.x;
    const int wid = tid >> 5, tx = tid & 31;
    const long long row0 = (long long)blockIdx.x * TM;

    // --- stage latents as fp16 (d,d+1) pairs ---
    {
        const float4* lat4 = (const float4*)(latents + row0 * D_DIM);
#pragma unroll
        for (int it = 0; it < 8; ++it) {
            int idx = it * NTHREADS + tid;      // 2048 float4
            int row = idx >> 5, c4 = idx & 31;
            float4 x = lat4[idx];
            s_lath[row * 64 + c4 * 2]     = __floats2half2_rn(x.x, x.y);
            s_lath[row * 64 + c4 * 2 + 1] = __floats2half2_rn(x.z, x.w);
        }
    }
    // --- rowsq: exact sequential reference chain (rescue/cm only) ---
    if (tid < TM) {
        const float* lr = latents + (row0 + tid) * D_DIM;
        float s = 0.f;
        for (int d = 0; d < D_DIM; ++d)
            s = __fadd_rn(s, __fmul_rn(lr[d], lr[d]));
        s_rowsq[tid] = s;
    }

    // --- fill: 2 threads per k-row, 64 d each; fp16 x256 into k-major rows ---
    auto fill = [&](int s, int buf) {
        int t = tid >> 1, p = tid & 1;
        const float4* src = (const float4*)emb + (size_t)(s * 128 + t) * 32 + p * 16;
        unsigned char* dst = smem + OFF_EMB + buf * EBUF + t * ESTR + p * 128;
        float ep = 0.f;
#pragma unroll
        for (int jj = 0; jj < 16; ++jj) {
            float4 v = src[jj];
            ep += v.x * v.x + v.y * v.y + v.z * v.z + v.w * v.w;
            union { __half2 h[2]; uint2 u; } pk;
            pk.h[0] = __floats2half2_rn(v.x * 256.f, v.y * 256.f);
            pk.h[1] = __floats2half2_rn(v.z * 256.f, v.w * 256.f);
            *(uint2*)(dst + jj * 8) = pk.u;
        }
        ep += __shfl_xor_sync(0xffffffffu, ep, 1);
        if (p == 0) s_esq[s * 128 + t] = ep;
    };

    const int r0 = wid * 8;     // 8 rows per warp
    float usum[8], umax[8];
#pragma unroll
    for (int i = 0; i < 8; ++i) { usum[i] = 0.f; umax[i] = 0.f; }
    const __half2 hz = __float2half2_rn(0.f);

    const unsigned char* aBase = smem + OFF_LATH + (size_t)r0 * ALSTR;

    fill(0, 0);

    // ---- 4 stages of 128 k: double-buffered fill, R8xC4 HFMA2 GEMM, u -> fp16 ----
#pragma unroll 1
    for (int s = 0; s < 4; ++s) {
        __syncthreads();            // fill(s) visible; frees buf (s+1)&1 for refill
        if (s < 3) fill(s + 1, (s + 1) & 1);

        const unsigned char* bBase = smem + OFF_EMB + (s & 1) * EBUF + (size_t)tx * ESTR;

        float accF[8][4];
        __half2 accH[8][4];
#pragma unroll
        for (int i = 0; i < 8; ++i)
#pragma unroll
            for (int j = 0; j < 4; ++j) { accF[i][j] = 0.f; accH[i][j] = hz; }

#pragma unroll 1
        for (int chunk = 0; chunk < 4; ++chunk) {
#pragma unroll
            for (int d4 = 0; d4 < 8; ++d4) {
                int off = (chunk * 8 + d4) * 8;          // 4 d values per iter
                union { __half2 h[2]; uint2 u; } av[8], bv[4];
#pragma unroll
                for (int i = 0; i < 8; ++i)
                    av[i].u = *(const uint2*)(aBase + i * ALSTR + off);   // broadcast
#pragma unroll
                for (int j = 0; j < 4; ++j)
                    bv[j].u = *(const uint2*)(bBase + j * (32 * ESTR) + off);
#pragma unroll
                for (int i = 0; i < 8; ++i)
#pragma unroll
                    for (int j = 0; j < 4; ++j) {
                        accH[i][j] = __hfma2(av[i].h[0], bv[j].h[0], accH[i][j]);
                        accH[i][j] = __hfma2(av[i].h[1], bv[j].h[1], accH[i][j]);
                    }
            }
            // promote to fp32 every 32 d (validated error budget)
#pragma unroll
            for (int i = 0; i < 8; ++i)
#pragma unroll
                for (int j = 0; j < 4; ++j) {
                    float2 f = __half22float2(accH[i][j]);
                    accF[i][j] += f.x + f.y;
                    accH[i][j] = hz;
                }
        }

        // u = exp(-10 * (esq - dotS/128)) -> fp16 smem; track sum/max per row
#pragma unroll
        for (int j = 0; j < 4; ++j) {
            int k = s * 128 + tx + 32 * j;
            float es = s_esq[k];
#pragma unroll
            for (int i = 0; i < 8; ++i) {
                float dsh = __fmaf_rn(accF[i][j], -0.0078125f, es);
                float u = __expf(-BETA_SM * dsh);
                s_uh[(r0 + i) * USTRH + k] = __float2half_rn(u);
                usum[i] += u;
                umax[i] = fmaxf(umax[i], u);
            }
        }
    }

    // ---- warp-reduce per-row sum/max ----
#pragma unroll
    for (int i = 0; i < 8; ++i)
#pragma unroll
        for (int o = 16; o; o >>= 1) {
            usum[i] += __shfl_xor_sync(0xffffffffu, usum[i], o);
            umax[i] = fmaxf(umax[i], __shfl_xor_sync(0xffffffffu, umax[i], o));
        }

    // ---- phase 2: probs, exact-rescue argmin, outputs ----
    float warp_sq = 0.f, warp_cm = 0.f;

#pragma unroll 1
    for (int i = 0; i < 8; ++i) {
        int r = r0 + i;
        long long rg = row0 + r;
        const __half* ur = s_uh + r * USTRH;
        float inv = 1.0f / usum[i];
        float thr = umax[i] * 0.994f;       // dist margin ~6e-4 (validated r12/r13)

        float* os = out_soft + rg * K_DIM;
        const float rsq = s_rowsq[r];
        const float* lrow = latents + rg * D_DIM;
        float bestd = 3.4e38f;
        int bestk = 0x7fffffff;
#pragma unroll 1
        for (int t = 0; t < 16; ++t) {
            int k = tx + 32 * t;
            float uv = __half2float(ur[k]);
            os[k] = uv * inv;
            if (uv >= thr) {
                // exact sequential-chain recompute on the reference grid
                const float* er = emb + (size_t)k * D_DIM;
                float a = 0.f, qq = 0.f;
                for (int d = 0; d < D_DIM; ++d) {
                    float ev = er[d];
                    a = __fmaf_rn(lrow[d], ev, a);
                    qq = __fadd_rn(qq, __fmul_rn(ev, ev));
                }
                float de = __fmaf_rn(-2.f, a, __fadd_rn(rsq, qq));
                if (de < bestd || (de == bestd && k < bestk)) { bestd = de; bestk = k; }
            }
        }
#pragma unroll
        for (int o = 16; o; o >>= 1) {
            float od = __shfl_xor_sync(0xffffffffu, bestd, o);
            int   ok = __shfl_xor_sync(0xffffffffu, bestk, o);
            if (od < bestd || (od == bestd && ok < bestk)) { bestd = od; bestk = ok; }
        }

        if (tx == 0) {
            atomicAdd(&g_counts[bestk], 1u);
            out_ind[rg] = (float)bestk;
            warp_cm += bestd;
        }

        float4 qv = ((const float4*)emb)[bestk * 32 + tx];
        float4 lv = ((const float4*)lrow)[tx];
        ((float4*)(out_q + rg * D_DIM))[tx] = qv;
        float dx = qv.x - lv.x, dy = qv.y - lv.y, dz = qv.z - lv.z, dw = qv.w - lv.w;
        float sq = dx * dx + dy * dy + dz * dz + dw * dw;
#pragma unroll
        for (int o = 16; o; o >>= 1) sq += __shfl_xor_sync(0xffffffffu, sq, o);
        if (tx == 0) warp_sq += sq;
    }

    if (tx == 0) {
        atomicAdd(&g_sq_sum, (double)warp_sq);
        atomicAdd(&g_mind_sum, (double)warp_cm);
    }

    // ---- last-block finalize: scalars + reset globals ----
    __shared__ int s_last;
    __threadfence();
    __syncthreads();
    if (tid == 0) {
        unsigned int t = atomicAdd(&g_done, 1u);
        s_last = (t == gridDim.x - 1u) ? 1 : 0;
    }
    __syncthreads();
    if (s_last) {
        __threadfence();
        float* red = (float*)smem;   // reuse u space
        double Bd = (double)gridDim.x * TM;
        float Bf = (float)Bd;
        float p0 = (float)g_counts[tid] / Bf;
        float p1 = (float)g_counts[tid + 256] / Bf;
        red[tid] = -p0 * logf(p0 + 1e-10f) - p1 * logf(p1 + 1e-10f);
        g_counts[tid] = 0u;
        g_counts[tid + 256] = 0u;
        __syncthreads();
        for (int s = 128; s > 0; s >>= 1) {
            if (tid < s) red[tid] += red[tid + s];
            __syncthreads();
        }
        if (tid == 0) {
            out_vq[0]  = (float)((g_sq_sum / (Bd * (double)D_DIM)) * 1.25);
            out_ent[0] = red[0];
            out_cm[0]  = (float)(g_mind_sum / Bd);
            g_sq_sum = 0.0;
            g_mind_sum = 0.0;
            g_done = 0u;
        }
    }
}

extern "C" void kernel_launch(void* const* d_in, const int* in_sizes, int n_in,
                              void* d_out, int out_size)
{
    const float* latents = (const float*)d_in[0];
    const float* emb     = (const float*)d_in[1];
    long long B = (long long)in_sizes[0] / D_DIM;

    float* out      = (float*)d_out;
    float* out_q    = out;
    float* out_vq   = out + B * D_DIM;
    float* out_ent  = out_vq + 1;
    float* out_ind  = out_ent + 1;
    float* out_soft = out_ind + B;
    float* out_cm   = out_soft + B * K_DIM;

    cudaFuncSetAttribute(vq_kernel, cudaFuncAttributeMaxDynamicSharedMemorySize, SMEM_BYTES);

    vq_kernel<<<(unsigned)(B / TM), NTHREADS, SMEM_BYTES>>>(
        latents, emb, out_q, out_ind, out_soft, out_vq, out_ent, out_cm);
}

// round 15
// speedup vs baseline: 1.2010x; 1.2010x over previous
#include <cuda_runtime.h>
#include <cuda_fp16.h>
#include <math.h>
#include <stdint.h>

#define D_DIM 128
#define K_DIM 512
#define TM 64
#define NTHREADS 256
#define BETA_SM 10.0f

// dynamic smem byte offsets
#define USTRH 520                    // u row stride (halves) -> 1040 B
#define OFF_U 0                      // 64 x 1040 = 66560
#define OFF_LATH 66560               // 64 x 256 = 16384
#define ALSTR 256
#define OFF_EMB  82944               // 512 x 264 = 135168 (ALL of emb, fp16 x256)
#define ESTR 264
#define OFF_ESQ  218112              // 512 x 4 = 2048
#define OFF_ROWSQ 220160             // 64 x 4 = 256
#define SMEM_BYTES 220416            // 1 CTA/SM

// ---------------- device globals (zero at load; self-reset each call) ----------------
__device__ double g_sq_sum;
__device__ double g_mind_sum;
__device__ unsigned int g_counts[K_DIM];
__device__ unsigned int g_done;

// ---------------- single fused kernel ----------------
__global__ void __launch_bounds__(NTHREADS, 1) vq_kernel(
    const float* __restrict__ latents,
    const float* __restrict__ emb,
    float* __restrict__ out_q,
    float* __restrict__ out_ind,
    float* __restrict__ out_soft,
    float* __restrict__ out_vq,
    float* __restrict__ out_ent,
    float* __restrict__ out_cm)
{
    extern __shared__ __align__(16) unsigned char smem[];
    __half*  s_uh    = (__half*)smem;                      // 64 x USTRH
    __half2* s_lath  = (__half2*)(smem + OFF_LATH);        // 64 x 64 (256 B rows)
    float*   s_esq   = (float*)(smem + OFF_ESQ);           // 512 (approx)
    float*   s_rowsq = (float*)(smem + OFF_ROWSQ);         // 64 (exact chains)

    __shared__ int   s_task[8][8][4];   // [warp][row][slot] candidate k
    __shared__ int   s_cnt[8][8];       // candidate count per row
    __shared__ float s_tde[8][8];       // per-row best exact dist
    __shared__ int   s_tk[8][8];        // per-row best k
    __shared__ int   s_lastF;

    const int tid = threadIdx.x;
    const int wid = tid >> 5, tx = tid & 31;
    const long long row0 = (long long)blockIdx.x * TM;

    // --- stage latents as fp16 (d,d+1) pairs ---
    {
        const float4* lat4 = (const float4*)(latents + row0 * D_DIM);
#pragma unroll
        for (int it = 0; it < 8; ++it) {
            int idx = it * NTHREADS + tid;      // 2048 float4
            int row = idx >> 5, c4 = idx & 31;
            float4 x = lat4[idx];
            s_lath[row * 64 + c4 * 2]     = __floats2half2_rn(x.x, x.y);
            s_lath[row * 64 + c4 * 2 + 1] = __floats2half2_rn(x.z, x.w);
        }
    }
    // --- rowsq: exact sequential reference chain (rescue/cm only) ---
    if (tid < TM) {
        const float* lr = latents + (row0 + tid) * D_DIM;
        float s = 0.f;
        for (int d = 0; d < D_DIM; ++d)
            s = __fadd_rn(s, __fmul_rn(lr[d], lr[d]));
        s_rowsq[tid] = s;
    }
    // --- load ALL emb into smem: fp16 x256 k-major (validated fill math) ---
    {
        int t = tid >> 1, p = tid & 1;
#pragma unroll 1
        for (int s = 0; s < 4; ++s) {
            const float4* src = (const float4*)emb + (size_t)(s * 128 + t) * 32 + p * 16;
            unsigned char* dst = smem + OFF_EMB + (s * 128 + t) * ESTR + p * 128;
            float ep = 0.f;
#pragma unroll
            for (int jj = 0; jj < 16; ++jj) {
                float4 v = src[jj];
                ep += v.x * v.x + v.y * v.y + v.z * v.z + v.w * v.w;
                union { __half2 h[2]; uint2 u; } pk;
                pk.h[0] = __floats2half2_rn(v.x * 256.f, v.y * 256.f);
                pk.h[1] = __floats2half2_rn(v.z * 256.f, v.w * 256.f);
                *(uint2*)(dst + jj * 8) = pk.u;
            }
            ep += __shfl_xor_sync(0xffffffffu, ep, 1);
            if (p == 0) s_esq[s * 128 + t] = ep;
        }
    }
    __syncthreads();   // the ONLY pre-GEMM barrier

    const int r0 = wid * 8;
    float usum[8], umax[8];
#pragma unroll
    for (int i = 0; i < 8; ++i) { usum[i] = 0.f; umax[i] = 0.f; }
    const __half2 hz = __float2half2_rn(0.f);
    const unsigned char* aBase = smem + OFF_LATH + (size_t)r0 * ALSTR;

    // ---- GEMM: 8 k-passes (64 cols each), R8xC2, barrier-free ----
#pragma unroll 1
    for (int pass = 0; pass < 8; ++pass) {
        const unsigned char* bB0 = smem + OFF_EMB + (size_t)(pass * 64 + tx) * ESTR;
        const unsigned char* bB1 = bB0 + 32 * ESTR;

        float accF[8][2];
        __half2 accH[8][2];
#pragma unroll
        for (int i = 0; i < 8; ++i)
#pragma unroll
            for (int j = 0; j < 2; ++j) { accF[i][j] = 0.f; accH[i][j] = hz; }

#pragma unroll 1
        for (int chunk = 0; chunk < 2; ++chunk) {       // 64 d per chunk
#pragma unroll
            for (int d8 = 0; d8 < 8; ++d8) {            // 8 d per iter
                int off = chunk * 128 + d8 * 16;
                union { __half2 h[4]; uint4 u; } av[8];
                union { __half2 h[2]; uint2 u; } b0a, b0b, b1a, b1b;
#pragma unroll
                for (int i = 0; i < 8; ++i)
                    av[i].u = *(const uint4*)(aBase + i * ALSTR + off);   // broadcast, 1 wf
                b0a.u = *(const uint2*)(bB0 + off);
                b0b.u = *(const uint2*)(bB0 + off + 8);
                b1a.u = *(const uint2*)(bB1 + off);
                b1b.u = *(const uint2*)(bB1 + off + 8);
#pragma unroll
                for (int i = 0; i < 8; ++i) {
                    accH[i][0] = __hfma2(av[i].h[0], b0a.h[0], accH[i][0]);
                    accH[i][0] = __hfma2(av[i].h[1], b0a.h[1], accH[i][0]);
                    accH[i][0] = __hfma2(av[i].h[2], b0b.h[0], accH[i][0]);
                    accH[i][0] = __hfma2(av[i].h[3], b0b.h[1], accH[i][0]);
                    accH[i][1] = __hfma2(av[i].h[0], b1a.h[0], accH[i][1]);
                    accH[i][1] = __hfma2(av[i].h[1], b1a.h[1], accH[i][1]);
                    accH[i][1] = __hfma2(av[i].h[2], b1b.h[0], accH[i][1]);
                    accH[i][1] = __hfma2(av[i].h[3], b1b.h[1], accH[i][1]);
                }
                if ((d8 & 3) == 3) {   // promote to fp32 every 32 d (validated budget)
#pragma unroll
                    for (int i = 0; i < 8; ++i)
#pragma unroll
                        for (int j = 0; j < 2; ++j) {
                            float2 f = __half22float2(accH[i][j]);
                            accF[i][j] += f.x + f.y;
                            accH[i][j] = hz;
                        }
                }
            }
        }

        // u = exp(-10 * (esq - dotS/128)) -> fp16 smem; track sum/max per row
#pragma unroll
        for (int j = 0; j < 2; ++j) {
            int k = pass * 64 + tx + 32 * j;
            float es = s_esq[k];
#pragma unroll
            for (int i = 0; i < 8; ++i) {
                float dsh = __fmaf_rn(accF[i][j], -0.0078125f, es);
                float u = __expf(-BETA_SM * dsh);
                s_uh[(r0 + i) * USTRH + k] = __float2half_rn(u);
                usum[i] += u;
                umax[i] = fmaxf(umax[i], u);
            }
        }
    }

    // ---- warp-reduce per-row sum/max ----
#pragma unroll
    for (int i = 0; i < 8; ++i)
#pragma unroll
        for (int o = 16; o; o >>= 1) {
            usum[i] += __shfl_xor_sync(0xffffffffu, usum[i], o);
            umax[i] = fmaxf(umax[i], __shfl_xor_sync(0xffffffffu, umax[i], o));
        }

    // ---- phase 2: probs writes + candidate collection (ballot) ----
    s_task[wid][tx >> 2][tx & 3] = -1;
    __syncwarp();

    float thrs[8];
#pragma unroll 1
    for (int i = 0; i < 8; ++i) {
        int r = r0 + i;
        long long rg = row0 + r;
        const __half* ur = s_uh + r * USTRH;
        float inv = 1.0f / usum[i];
        float thr = umax[i] * 0.994f;       // dist margin ~6e-4 (validated r12/r13)
        thrs[i] = thr;
        float* os = out_soft + rg * K_DIM;
        int nrow = 0;
#pragma unroll
        for (int t = 0; t < 16; ++t) {
            int k = tx + 32 * t;
            float uv = __half2float(ur[k]);
            os[k] = uv * inv;
            bool c = (uv >= thr);
            unsigned bal = __ballot_sync(0xffffffffu, c);
            if (c) {
                int idx = nrow + __popc(bal & ((1u << tx) - 1u));
                if (idx < 4) s_task[wid][i][idx] = k;
            }
            nrow += __popc(bal);
        }
        if (tx == 0) s_cnt[wid][i] = nrow;
    }
    __syncwarp();

    // ---- parallel exact rescue: 32 lanes <- 8 rows x 4 slots ----
    {
        int prow = tx >> 2;
        int k = s_task[wid][prow][tx & 3];
        float de = 3.4e38f;
        int kk = 0x7fffffff;
        if (k >= 0) {
            const float* er = emb + (size_t)k * D_DIM;
            const float* lr = latents + (row0 + r0 + prow) * D_DIM;
            float a = 0.f, qq = 0.f;
            for (int d = 0; d < D_DIM; ++d) {
                float ev = er[d];
                a = __fmaf_rn(lr[d], ev, a);
                qq = __fadd_rn(qq, __fmul_rn(ev, ev));
            }
            de = __fmaf_rn(-2.f, a, __fadd_rn(s_rowsq[r0 + prow], qq));
            kk = k;
        }
#pragma unroll
        for (int o = 1; o <= 2; o <<= 1) {   // reduce within 4-lane slot group
            float od = __shfl_xor_sync(0xffffffffu, de, o);
            int   ok = __shfl_xor_sync(0xffffffffu, kk, o);
            if (od < de || (od == de && ok < kk)) { de = od; kk = ok; }
        }
        if ((tx & 3) == 0) { s_tde[wid][prow] = de; s_tk[wid][prow] = kk; }
    }
    __syncwarp();

    // ---- per-row outputs (overflow rows fall back to full serial rescue) ----
    float warp_sq = 0.f, warp_cm = 0.f;
#pragma unroll 1
    for (int i = 0; i < 8; ++i) {
        int r = r0 + i;
        long long rg = row0 + r;
        float bestd = s_tde[wid][i];
        int bestk = s_tk[wid][i];

        if (s_cnt[wid][i] > 4) {    // rare: redo full serial rescue for this row
            const __half* ur = s_uh + r * USTRH;
            const float rsq = s_rowsq[r];
            const float* lrow = latents + rg * D_DIM;
            float bd = 3.4e38f; int bk = 0x7fffffff;
#pragma unroll 1
            for (int t = 0; t < 16; ++t) {
                int k = tx + 32 * t;
                if (__half2float(ur[k]) >= thrs[i]) {
                    const float* er = emb + (size_t)k * D_DIM;
                    float a = 0.f, qq = 0.f;
                    for (int d = 0; d < D_DIM; ++d) {
                        float ev = er[d];
                        a = __fmaf_rn(lrow[d], ev, a);
                        qq = __fadd_rn(qq, __fmul_rn(ev, ev));
                    }
                    float de = __fmaf_rn(-2.f, a, __fadd_rn(rsq, qq));
                    if (de < bd || (de == bd && k < bk)) { bd = de; bk = k; }
                }
            }
#pragma unroll
            for (int o = 16; o; o >>= 1) {
                float od = __shfl_xor_sync(0xffffffffu, bd, o);
                int   ok = __shfl_xor_sync(0xffffffffu, bk, o);
                if (od < bd || (od == bd && ok < bk)) { bd = od; bk = ok; }
            }
            bestd = bd; bestk = bk;
        }

        if (tx == 0) {
            atomicAdd(&g_counts[bestk], 1u);
            out_ind[rg] = (float)bestk;
            warp_cm += bestd;
        }

        float4 qv = ((const float4*)emb)[bestk * 32 + tx];
        float4 lv = ((const float4*)(latents + rg * D_DIM))[tx];
        ((float4*)(out_q + rg * D_DIM))[tx] = qv;
        float dx = qv.x - lv.x, dy = qv.y - lv.y, dz = qv.z - lv.z, dw = qv.w - lv.w;
        float sq = dx * dx + dy * dy + dz * dz + dw * dw;
#pragma unroll
        for (int o = 16; o; o >>= 1) sq += __shfl_xor_sync(0xffffffffu, sq, o);
        if (tx == 0) warp_sq += sq;
    }

    if (tx == 0) {
        atomicAdd(&g_sq_sum, (double)warp_sq);
        atomicAdd(&g_mind_sum, (double)warp_cm);
    }

    // ---- last-block finalize: scalars + reset globals ----
    __threadfence();
    __syncthreads();
    if (tid == 0) {
        unsigned int t = atomicAdd(&g_done, 1u);
        s_lastF = (t == gridDim.x - 1u) ? 1 : 0;
    }
    __syncthreads();
    if (s_lastF) {
        __threadfence();
        float* red = (float*)smem;   // reuse u space
        double Bd = (double)gridDim.x * TM;
        float Bf = (float)Bd;
        float p0 = (float)g_counts[tid] / Bf;
        float p1 = (float)g_counts[tid + 256] / Bf;
        red[tid] = -p0 * logf(p0 + 1e-10f) - p1 * logf(p1 + 1e-10f);
        g_counts[tid] = 0u;
        g_counts[tid + 256] = 0u;
        __syncthreads();
        for (int s = 128; s > 0; s >>= 1) {
            if (tid < s) red[tid] += red[tid + s];
            __syncthreads();
        }
        if (tid == 0) {
            out_vq[0]  = (float)((g_sq_sum / (Bd * (double)D_DIM)) * 1.25);
            out_ent[0] = red[0];
            out_cm[0]  = (float)(g_mind_sum / Bd);
            g_sq_sum = 0.0;
            g_mind_sum = 0.0;
            g_done = 0u;
        }
    }
}

extern "C" void kernel_launch(void* const* d_in, const int* in_sizes, int n_in,
                              void* d_out, int out_size)
{
    const float* latents = (const float*)d_in[0];
    const float* emb     = (const float*)d_in[1];
    long long B = (long long)in_sizes[0] / D_DIM;

    float* out      = (float*)d_out;
    float* out_q    = out;
    float* out_vq   = out + B * D_DIM;
    float* out_ent  = out_vq + 1;
    float* out_ind  = out_ent + 1;
    float* out_soft = out_ind + B;
    float* out_cm   = out_soft + B * K_DIM;

    cudaFuncSetAttribute(vq_kernel, cudaFuncAttributeMaxDynamicSharedMemorySize, SMEM_BYTES);

    vq_kernel<<<(unsigned)(B / TM), NTHREADS, SMEM_BYTES>>>(
        latents, emb, out_q, out_ind, out_soft, out_vq, out_ent, out_cm);
}

// round 17
// speedup vs baseline: 1.6118x; 1.3420x over previous
#include <cuda_runtime.h>
#include <cuda_fp16.h>
#include <math.h>
#include <stdint.h>

#define D_DIM 128
#define K_DIM 512
#define TM 64            // latent rows per block
#define KH 256           // k per half
#define DS 32            // d per stage
#define NTHREADS 256
#define LSTRIDE 132      // s_lat row stride (floats); rowsq stashed at [r][128]
#define ESTR 258         // s_embT row stride (floats)
#define USTRH 520        // u row stride (halves)

// smem byte offsets
#define OFF_UH 0                         // 64 x 520 x 2 = 66560
#define OFF_LAT 66560                    // 64 x 132 x 4 = 33792
#define OFF_EMBT0 100352                 // 32 x 258 x 4 = 33024
#define OFF_EMBT1 133376                 // 33024
#define OFF_ESQ 166400                   // 512 x 4 = 2048
#define SMEM_BYTES 168448

// ---------------- device globals ----------------
__device__ double g_sq_sum;
__device__ double g_mind_sum;
__device__ unsigned int g_counts[K_DIM];
__device__ float g_emb_sq[K_DIM];
__device__ unsigned int g_done;

__device__ __forceinline__ void fma2(unsigned long long& d, unsigned long long a,
                                     unsigned long long b, unsigned long long c) {
    asm("fma.rn.f32x2 %0, %1, %2, %3;" : "=l"(d) : "l"(a), "l"(b), "l"(c));
}
__device__ __forceinline__ unsigned long long pack2(float lo, float hi) {
    unsigned long long r;
    asm("mov.b64 %0, {%1, %2};" : "=l"(r) : "f"(lo), "f"(hi));
    return r;
}
__device__ __forceinline__ void unpack2(float& lo, float& hi, unsigned long long v) {
    asm("mov.b64 {%0, %1}, %2;" : "=f"(lo), "=f"(hi) : "l"(v));
}

// ---------------- init: zero accumulators, exact ||e_k||^2 chains ----------------
__global__ void vq_init_kernel(const float* __restrict__ emb) {
    int k = blockIdx.x * 32 + threadIdx.x;   // grid 16 x 32
    if (k == 0) { g_sq_sum = 0.0; g_mind_sum = 0.0; g_done = 0u; }
    g_counts[k] = 0u;
    const float* e = emb + (size_t)k * D_DIM;
    float s = 0.f;
    for (int i = 0; i < D_DIM; ++i)
        s = __fadd_rn(s, __fmul_rn(e[i], e[i]));
    g_emb_sq[k] = s;
}

// ---------------- main kernel (round-4 GEMM verbatim; fused epilogue) ----------------
__global__ void __launch_bounds__(NTHREADS, 1) vq_main_kernel(
    const float* __restrict__ latents,
    const float* __restrict__ emb,
    float* __restrict__ out_q,
    float* __restrict__ out_ind,
    float* __restrict__ out_soft,
    float* __restrict__ out_vq,
    float* __restrict__ out_ent,
    float* __restrict__ out_cm)
{
    extern __shared__ __align__(16) unsigned char smem[];
    __half* s_uh  = (__half*)smem;                            // 64 x USTRH
    float*  s_lat = (float*)(smem + OFF_LAT);                 // 64 x LSTRIDE
    float*  s_embT[2] = { (float*)(smem + OFF_EMBT0), (float*)(smem + OFF_EMBT1) };
    float*  s_esq = (float*)(smem + OFF_ESQ);                 // 512
    __shared__ int s_lastF;

    const int tid = threadIdx.x;
    const int tx = tid & 31;   // k-lane
    const int ty = tid >> 5;   // warp id / row-group
    const long long row0 = (long long)blockIdx.x * TM;

    // --- load latent tile (coalesced float4 -> padded smem) + esq stage ---
    {
        const float4* g = (const float4*)(latents + row0 * D_DIM);
#pragma unroll
        for (int it = 0; it < (TM * D_DIM / 4) / NTHREADS; ++it) {
            int idx = it * NTHREADS + tid;
            int r = idx >> 5, c4 = idx & 31;
            *(float4*)(s_lat + r * LSTRIDE + c4 * 4) = g[idx];
        }
        s_esq[tid] = g_emb_sq[tid];
        s_esq[256 + tid] = g_emb_sq[256 + tid];
    }
    __syncthreads();

    // --- rowsq: exact sequential reference chains, stashed in row padding ---
    if (tid < TM) {
        const float* lr = s_lat + tid * LSTRIDE;
        float s = 0.f;
#pragma unroll 16
        for (int i = 0; i < D_DIM; ++i)
            s = __fadd_rn(s, __fmul_rn(lr[i], lr[i]));
        s_lat[tid * LSTRIDE + D_DIM] = s;
    }

    // --- transposed emb stage fill: tile = KH k x DS d (round-4 verbatim) ---
    const float4* e4 = (const float4*)emb;
    auto fill = [&](int buf, int kh, int ds) {
        float* sb = s_embT[buf];
#pragma unroll
        for (int it = 0; it < (KH * DS / 4) / NTHREADS; ++it) {   // 8 iters
            int idx = it * NTHREADS + tid;
            int k = idx >> 3;           // 0..255
            int d4l = idx & 7;          // 0..7
            float4 v = e4[(size_t)(kh * KH + k) * (D_DIM / 4) + ds * (DS / 4) + d4l];
            float* c = sb + (4 * d4l) * ESTR + k;
            c[0 * ESTR] = v.x; c[1 * ESTR] = v.y; c[2 * ESTR] = v.z; c[3 * ESTR] = v.w;
        }
    };

    fill(0, 0, 0);
    __syncthreads();

    // per-row online state
    float usum[8], bv[8];
    int bk[8];
#pragma unroll
    for (int i = 0; i < 8; ++i) { usum[i] = 0.f; bv[i] = 3.4e38f; bk[i] = 0; }

    // --- GEMM: dist = fl( fl(rowsq+embsq) - 2*(l.e) ), ascending-d FMA chain (r4 verbatim) ---
    for (int kh = 0; kh < 2; ++kh) {
        unsigned long long acc[8][4];
#pragma unroll
        for (int i = 0; i < 8; ++i)
#pragma unroll
            for (int p = 0; p < 4; ++p) acc[i][p] = 0ull;

        for (int ds = 0; ds < 4; ++ds) {
            if (ds < 3)            fill((ds + 1) & 1, kh, ds + 1);
            else if (kh == 0)      fill(0, 1, 0);

            const float* sb = s_embT[ds & 1];
#pragma unroll
            for (int j = 0; j < 8; ++j) {
                float4 a4[8];
                const float* lp = s_lat + ty * 8 * LSTRIDE + (ds * DS + 4 * j);
#pragma unroll
                for (int i = 0; i < 8; ++i) a4[i] = *(const float4*)(lp + i * LSTRIDE);
#pragma unroll
                for (int dd = 0; dd < 4; ++dd) {
                    unsigned long long bp[4];
                    const float* bb = sb + (4 * j + dd) * ESTR + 2 * tx;
#pragma unroll
                    for (int p = 0; p < 4; ++p)
                        bp[p] = *(const unsigned long long*)(bb + 64 * p);
#pragma unroll
                    for (int i = 0; i < 8; ++i) {
                        float as = (dd == 0) ? a4[i].x : (dd == 1) ? a4[i].y
                                 : (dd == 2) ? a4[i].z : a4[i].w;
                        unsigned long long av = pack2(as, as);
#pragma unroll
                        for (int p = 0; p < 4; ++p)
                            fma2(acc[i][p], av, bp[p], acc[i][p]);
                    }
                }
            }
            __syncthreads();
        }

        // store phase: exact dist -> online argmin + u = exp(-10(d - rowsq)) fp16
#pragma unroll
        for (int i = 0; i < 8; ++i) {
            int r = ty * 8 + i;
            float rs = s_lat[r * LSTRIDE + D_DIM];
#pragma unroll
            for (int p = 0; p < 4; ++p) {
                int k = kh * KH + 64 * p + 2 * tx;
                float lo, hi; unpack2(lo, hi, acc[i][p]);
                float2 es = *(const float2*)(s_esq + k);
                float t0 = __fadd_rn(rs, es.x);
                float t1 = __fadd_rn(rs, es.y);
                float d0 = __fmaf_rn(-2.0f, lo, t0);     // exact reference grid
                float d1 = __fmaf_rn(-2.0f, hi, t1);
                if (d0 < bv[i]) { bv[i] = d0; bk[i] = k; }       // ascending k -> lowest index
                if (d1 < bv[i]) { bv[i] = d1; bk[i] = k + 1; }
                float u0 = __expf(-10.0f * (d0 - rs));
                float u1 = __expf(-10.0f * (d1 - rs));
                usum[i] += u0 + u1;
                *(__half2*)(s_uh + r * USTRH + k) = __floats2half2_rn(u0, u1);
            }
        }
    }

    // --- warp reductions per row: usum, argmin (lowest index on ties) ---
#pragma unroll
    for (int i = 0; i < 8; ++i) {
#pragma unroll
        for (int o = 16; o; o >>= 1) {
            usum[i] += __shfl_xor_sync(0xffffffffu, usum[i], o);
            float od = __shfl_xor_sync(0xffffffffu, bv[i], o);
            int   ok = __shfl_xor_sync(0xffffffffu, bk[i], o);
            if (od < bv[i] || (od == bv[i] && ok < bk[i])) { bv[i] = od; bk[i] = ok; }
        }
    }

    // --- epilogue: probs (float2 stores: out_soft is only 8B-aligned), indices, quantized ---
    float warp_sq = 0.f, warp_cm = 0.f;

#pragma unroll 1
    for (int i = 0; i < 8; ++i) {
        int r = ty * 8 + i;
        long long rg = row0 + r;
        float inv = 1.0f / usum[i];
        const __half* ur = s_uh + r * USTRH;
        float* os = out_soft + rg * K_DIM;
#pragma unroll
        for (int t = 0; t < 8; ++t) {
            int k0 = t * 64 + 2 * tx;
            __half2 uu = *(const __half2*)(ur + k0);
            float2 f = __half22float2(uu);
            float2 w;
            w.x = f.x * inv;
            w.y = f.y * inv;
            *(float2*)(os + k0) = w;
        }

        int bestk = bk[i];
        if (tx == 0) {
            atomicAdd(&g_counts[bestk], 1u);
            out_ind[rg] = (float)bestk;
            warp_cm += bv[i];                 // exact dist at argmin (reference grid)
        }

        float4 qv = ((const float4*)emb)[bestk * 32 + tx];
        float4 lv = *(const float4*)(s_lat + r * LSTRIDE + 4 * tx);
        ((float4*)(out_q + rg * D_DIM))[tx] = qv;
        float dx = qv.x - lv.x, dy = qv.y - lv.y, dz = qv.z - lv.z, dw = qv.w - lv.w;
        float sq = dx * dx + dy * dy + dz * dz + dw * dw;
#pragma unroll
        for (int o = 16; o; o >>= 1) sq += __shfl_xor_sync(0xffffffffu, sq, o);
        if (tx == 0) warp_sq += sq;
    }

    if (tx == 0) {
        atomicAdd(&g_sq_sum, (double)warp_sq);
        atomicAdd(&g_mind_sum, (double)warp_cm);
    }

    // ---- last-block finalize: scalars (init kernel re-zeroes globals next call) ----
    __threadfence();
    __syncthreads();
    if (tid == 0) {
        unsigned int t = atomicAdd(&g_done, 1u);
        s_lastF = (t == gridDim.x - 1u) ? 1 : 0;
    }
    __syncthreads();
    if (s_lastF) {
        __threadfence();
        float* red = (float*)smem;   // reuse u space
        double Bd = (double)gridDim.x * TM;
        float Bf = (float)Bd;
        float p0 = (float)g_counts[tid] / Bf;
        float p1 = (float)g_counts[tid + 256] / Bf;
        red[tid] = -p0 * logf(p0 + 1e-10f) - p1 * logf(p1 + 1e-10f);
        __syncthreads();
        for (int s = 128; s > 0; s >>= 1) {
            if (tid < s) red[tid] += red[tid + s];
            __syncthreads();
        }
        if (tid == 0) {
            out_vq[0]  = (float)((g_sq_sum / (Bd * (double)D_DIM)) * 1.25);
            out_ent[0] = red[0];
            out_cm[0]  = (float)(g_mind_sum / Bd);
        }
    }
}

extern "C" void kernel_launch(void* const* d_in, const int* in_sizes, int n_in,
                              void* d_out, int out_size)
{
    const float* latents = (const float*)d_in[0];
    const float* emb     = (const float*)d_in[1];
    long long B = (long long)in_sizes[0] / D_DIM;

    float* out      = (float*)d_out;
    float* out_q    = out;
    float* out_vq   = out + B * D_DIM;
    float* out_ent  = out_vq + 1;
    float* out_ind  = out_ent + 1;
    float* out_soft = out_ind + B;
    float* out_cm   = out_soft + B * K_DIM;

    cudaFuncSetAttribute(vq_main_kernel, cudaFuncAttributeMaxDynamicSharedMemorySize, SMEM_BYTES);

    vq_init_kernel<<<16, 32>>>(emb);
    vq_main_kernel<<<(unsigned)(B / TM), NTHREADS, SMEM_BYTES>>>(
        latents, emb, out_q, out_ind, out_soft, out_vq, out_ent, out_cm);
}